// round 15
// baseline (speedup 1.0000x reference)
#include <cuda_runtime.h>
#include <math.h>
#include <stdint.h>

#define NLAT 721
#define NLON 1440
#define NB   4
#define DT   0.01f
#define FOFF ((size_t)NB * NLAT * NLON)
#define DTH  (3.14159265358979323846 / 720.0)

#define LS     10
#define NPOLAR 20
#define NINT   701                       // rows 10..710
#define NCHB   4
#define NPOLTASK (NPOLAR * 3 * NCHB)     // 240

#define HALO  64
#define KW_A  (2 * HALO)                 // 128 floats per staged K row (interior)
#define SMW_A (NLON + 2 * HALO + 8)      // 1576 floats; row = 6304 B
#define SMW_B 2896                       // polar duplicated row; 11584 B
#define KW_B  368                        // max polar chunk taps (360) + pad
#define SMEM_CORE ((9 * SMW_A + 12 * KW_A) * 4)   // 62880 B (>= polar 40640)
#define MBAR_OFF  SMEM_CORE
#define SMEMSZ    (SMEM_CORE + 16)
#define BLK   384
#define COMP  360

static __device__ float g_c1[3 * FOFF];   // y0 + DT/2 k1
static __device__ float g_c2[3 * FOFF];   // y0 + DT/2 k2
static __device__ float g_c3[3 * FOFF];   // y0 + DT   k3
static __device__ float g_part[(size_t)(3 * NCHB) * NB * NPOLAR * 3 * NLON];
static __device__ int   g_bjl [NLAT * 3];
static __device__ int   g_bcnt[NLAT * 3];

__device__ __forceinline__ int polar_map(int rl) { return rl < 10 ? rl : 711 + (rl - 10); }

__device__ __forceinline__ uint32_t smem_u32(const void* p) {
    uint32_t a;
    asm("{ .reg .u64 t; cvta.to.shared.u64 t, %1; cvt.u32.u64 %0, t; }" : "=r"(a) : "l"(p));
    return a;
}
__device__ __forceinline__ void bulk_g2s(uint32_t dst, const void* src,
                                         uint32_t bytes, uint32_t mbar) {
    asm volatile(
        "cp.async.bulk.shared::cluster.global.mbarrier::complete_tx::bytes [%0], [%1], %2, [%3];"
        :: "r"(dst), "l"(src), "r"(bytes), "r"(mbar) : "memory");
}
__device__ __forceinline__ void mbar_init(uint32_t mbar, uint32_t cnt) {
    asm volatile("mbarrier.init.shared.b64 [%0], %1;" :: "r"(mbar), "r"(cnt) : "memory");
}
__device__ __forceinline__ void mbar_expect(uint32_t mbar, uint32_t bytes) {
    asm volatile("mbarrier.arrive.expect_tx.shared.b64 _, [%0], %1;"
                 :: "r"(mbar), "r"(bytes) : "memory");
}
__device__ __forceinline__ void mbar_wait(uint32_t mbar) {
    asm volatile(
        "{\n\t.reg .pred P;\n\t"
        "W_%=:\n\t"
        "mbarrier.try_wait.parity.acquire.cta.shared::cta.b64 P, [%0], 0, 0x989680;\n\t"
        "@P bra.uni D_%=;\n\t"
        "bra.uni W_%=;\n\t"
        "D_%=:\n\t}"
        :: "r"(mbar) : "memory");
}

__global__ void init_bounds()
{
    int idx = blockIdx.x * blockDim.x + threadIdx.x;
    if (idx >= NLAT * 3) return;
    int l = idx / 3, dd = idx - 3 * l;
    int jl = 0, cnt = 0;
    int lq = l - 1 + dd;
    if (lq >= 1 && lq <= NLAT - 2) {
        if (l == 0 || l == NLAT - 1) { jl = -720; cnt = 1440; }
        else {
            double tp = l * DTH, tq = lq * DTH;
            double cph = (cos(2.0 * DTH) - cos(tp) * cos(tq)) / (sin(tp) * sin(tq));
            if (cph < 1.0) {
                int W = 720;
                if (cph > -1.0) W = (int)(acos(cph) / DTH) + 1;
                if (W >= 716) { jl = -720; cnt = 1440; }
                else { jl = -((W + 3) & ~3); int je = (W + 4) & ~3; cnt = je - jl; }
            }
        }
    }
    g_bjl[idx] = jl; g_bcnt[idx] = cnt;
}

struct Acc { float adu[4], adv[4], adh[4]; };

// Correlation over j in [j0, j1), 4-aligned, all pointers into SMEM.
__device__ __forceinline__ void seg_loop(
    const float* kgc, const float* kgs, const float* kdc, const float* kds,
    const float* rh, const float* ru, const float* rv,
    int j0, int j1, Acc& a)
{
    if (j0 >= j1) return;
    float4 hA = *(const float4*)(rh + j0);
    float4 uA = *(const float4*)(ru + j0);
    float4 vA = *(const float4*)(rv + j0);
    for (int j = j0; j < j1; j += 4) {
        const float4 kc = *(const float4*)(kgc + j);
        const float4 ks = *(const float4*)(kgs + j);
        const float4 dc = *(const float4*)(kdc + j);
        const float4 dz = *(const float4*)(kds + j);
        float4 hB = *(const float4*)(rh + j + 4);
        float4 uB = *(const float4*)(ru + j + 4);
        float4 vB = *(const float4*)(rv + j + 4);
        float hb[8] = {hA.x,hA.y,hA.z,hA.w,hB.x,hB.y,hB.z,hB.w};
        float ub[8] = {uA.x,uA.y,uA.z,uA.w,uB.x,uB.y,uB.z,uB.w};
        float vb[8] = {vA.x,vA.y,vA.z,vA.w,vB.x,vB.y,vB.z,vB.w};
        float kcb[4] = {kc.x,kc.y,kc.z,kc.w};
        float ksb[4] = {ks.x,ks.y,ks.z,ks.w};
        float dcb[4] = {dc.x,dc.y,dc.z,dc.w};
        float dsb[4] = {dz.x,dz.y,dz.z,dz.w};
        #pragma unroll
        for (int jj = 0; jj < 4; ++jj)
            #pragma unroll
            for (int i = 0; i < 4; ++i) {
                a.adu[i] = fmaf(kcb[jj], hb[jj+i], a.adu[i]);
                a.adv[i] = fmaf(ksb[jj], hb[jj+i], a.adv[i]);
                a.adh[i] = fmaf(dcb[jj], ub[jj+i], a.adh[i]);
                a.adh[i] = fmaf(dsb[jj], vb[jj+i], a.adh[i]);
            }
        hA = hB; uA = uB; vA = vB;
    }
}

template<int STAGE>
__device__ __forceinline__ const float* src_base()
{
    return (STAGE == 2) ? g_c1 : (STAGE == 3) ? g_c2 : g_c3;
}

// RK epilogue. ch/cu/cv = stage-source center values (smem). For STAGE 1 they
// ARE y0 (source == initial state) -> no global y0 reads. For STAGE 4 they are
// c3 values used to reconstruct k3 without a global read.
template<int STAGE>
__device__ __forceinline__ void rk_epilogue(
    size_t idx, float kh, float ku, float kv,
    float ch, float cu, float cv,
    const float* __restrict__ h0, const float* __restrict__ uv0,
    float* __restrict__ outH, float* __restrict__ outUV)
{
    if (STAGE == 1) {
        g_c1[idx]        = ch + 0.5f*DT*kh;
        g_c1[FOFF+idx]   = cu + 0.5f*DT*ku;
        g_c1[2*FOFF+idx] = cv + 0.5f*DT*kv;
        return;
    }
    float y0h = h0[idx], y0u = uv0[2*idx], y0v = uv0[2*idx+1];
    if (STAGE == 2) {
        g_c2[idx]        = y0h + 0.5f*DT*kh;
        g_c2[FOFF+idx]   = y0u + 0.5f*DT*ku;
        g_c2[2*FOFF+idx] = y0v + 0.5f*DT*kv;
    } else if (STAGE == 3) {
        g_c3[idx]        = y0h + DT*kh;
        g_c3[FOFF+idx]   = y0u + DT*ku;
        g_c3[2*FOFF+idx] = y0v + DT*kv;
    } else {
        const float i2 = 2.0f / DT, i1 = 1.0f / DT;
        float k1h = (g_c1[idx]        - y0h) * i2;
        float k1u = (g_c1[FOFF+idx]   - y0u) * i2;
        float k1v = (g_c1[2*FOFF+idx] - y0v) * i2;
        float k2h = (g_c2[idx]        - y0h) * i2;
        float k2u = (g_c2[FOFF+idx]   - y0u) * i2;
        float k2v = (g_c2[2*FOFF+idx] - y0v) * i2;
        float k3h = (ch - y0h) * i1;
        float k3u = (cu - y0u) * i1;
        float k3v = (cv - y0v) * i1;
        outH[idx] = y0h + (DT/6.f) * (k1h + 2.f*k2h + 2.f*k3h + kh);
        float2 o;
        o.x = y0u + (DT/6.f) * (k1u + 2.f*k2u + 2.f*k3u + ku);
        o.y = y0v + (DT/6.f) * (k1v + 2.f*k2v + 2.f*k3v + kv);
        reinterpret_cast<float2*>(outUV)[idx] = o;
    }
}

template<int STAGE>
__global__ void __launch_bounds__(BLK, 3)
tend_kernel(const float* __restrict__ h0, const float* __restrict__ uv0,
            const float* __restrict__ Kgc, const float* __restrict__ Kgs,
            const float* __restrict__ Kdc, const float* __restrict__ Kds,
            const float* __restrict__ fcor,
            float* __restrict__ outH, float* __restrict__ outUV)
{
    extern __shared__ __align__(16) float sh[];
    int tid = threadIdx.x, bx = blockIdx.x, b = blockIdx.y;
    const float* Ks[4] = {Kgc, Kgs, Kdc, Kds};
    uint32_t shb  = smem_u32(sh);
    uint32_t mbar = shb + MBAR_OFF;

    if (tid == 0) mbar_init(mbar, 1);
    __syncthreads();

    if (bx < NPOLTASK) {
        // ---------------- polar chunk (rows 0..9, 711..720) ----------------
        int rl = bx / (3 * NCHB), rem = bx - rl * 3 * NCHB;
        int dd = rem / NCHB, c = rem - dd * NCHB;
        int l = polar_map(rl);
        int cnt = __ldg(&g_bcnt[l * 3 + dd]);
        int jl = __ldg(&g_bjl[l * 3 + dd]);
        int steps = cnt >> 2;
        int per = (steps + NCHB - 1) / NCHB;
        int s0 = c * per, s1 = min(steps, s0 + per);
        if (cnt == 0 || s0 >= s1) return;
        int jA = jl + 4 * s0, jB = jl + 4 * s1;
        int ntap = jB - jA;
        int neg_len = max(0, min(jB, 0) - jA);
        int pos_len = max(0, jB - max(jA, 0));

        int lq = l - 1 + dd;
        size_t rowg = (size_t)(b * NLAT + lq) * NLON;
        size_t ko   = (size_t)(l * 5 + dd + 1) * NLON;
        uint32_t shKo = shb + 3 * SMW_B * 4;

        // parallel TMA issue: fields (<=9 cmds) + K (<=8 cmds)
        {
            int nfld = (STAGE == 1) ? 1 : 3;
            if (tid == 0)
                mbar_expect(mbar, (uint32_t)nfld * 11520u + 16u * (uint32_t)ntap);
            if (tid < nfld * 3) {
                int f = tid / 3, p = tid - f * 3;
                const float* src = (STAGE == 1) ? (h0 + rowg)
                                                : (src_base<STAGE>() + (size_t)f * FOFF + rowg);
                uint32_t d = shb + f * SMW_B * 4;
                if (p == 0)      bulk_g2s(d,        src + 720, 2880, mbar);
                else if (p == 1) bulk_g2s(d + 2880, src,       5760, mbar);
                else             bulk_g2s(d + 8640, src,       2880, mbar);
            } else if (tid >= 32 && tid < 40) {
                int e2 = tid - 32;
                int k = e2 >> 1, p = e2 & 1;
                uint32_t d = shKo + k * KW_B * 4;
                if (p == 0) { if (neg_len > 0) bulk_g2s(d, Ks[k] + ko + NLON + jA, neg_len * 4, mbar); }
                else        { if (pos_len > 0) bulk_g2s(d + neg_len * 4, Ks[k] + ko + max(jA, 0), pos_len * 4, mbar); }
            }
        }
        if (STAGE == 1) {
            for (int e = tid; e < 2 * (NLON / 4); e += BLK) {
                int f = 1 + e / (NLON / 4);
                int m = (e - (f - 1) * (NLON / 4)) * 4;
                const float4 a4 = *(const float4*)(uv0 + 2 * (rowg + m));
                const float4 c4 = *(const float4*)(uv0 + 2 * (rowg + m) + 4);
                float4 x;
                if (f == 1) { x.x=a4.x; x.y=a4.z; x.z=c4.x; x.w=c4.z; }
                else        { x.x=a4.y; x.y=a4.w; x.z=c4.y; x.w=c4.w; }
                int q = m + 720; if (q >= NLON) q -= NLON;
                float* dst = sh + f * SMW_B;
                *(float4*)(dst + q) = x;
                *(float4*)(dst + q + NLON) = x;
            }
            __syncthreads();
        }
        mbar_wait(mbar);
        if (tid >= COMP) return;

        int n0 = tid * 4;
        Acc a;
        #pragma unroll
        for (int i = 0; i < 4; ++i) { a.adu[i]=0.f; a.adv[i]=0.f; a.adh[i]=0.f; }
        const float* shK = sh + 3 * SMW_B;
        seg_loop(shK + 0*KW_B - jA, shK + 1*KW_B - jA,
                 shK + 2*KW_B - jA, shK + 3*KW_B - jA,
                 sh + 720 + n0, sh + SMW_B + 720 + n0, sh + 2*SMW_B + 720 + n0,
                 jA, jB, a);

        int task = b * NPOLAR + rl;
        float* part = g_part + ((size_t)(dd * NCHB + c) * (NB * NPOLAR) + task) * (3 * NLON);
        *(float4*)(part + 0*NLON + n0) = *(float4*)a.adu;
        *(float4*)(part + 1*NLON + n0) = *(float4*)a.adv;
        *(float4*)(part + 2*NLON + n0) = *(float4*)a.adh;
    } else {
        // ---------------- interior full row (l in [10, 710]) ----------------
        int li = bx - NPOLTASK;
        int l = (li & 1) ? (710 - (li >> 1)) : (LS + (li >> 1));
        uint32_t shKo = shb + 9 * SMW_A * 4;

        // parallel TMA issue: field rows (3 or 9 rows x 3 pieces) + K (24 cmds)
        {
            int nrows = (STAGE == 1) ? 3 : 9;
            if (tid == 0)
                mbar_expect(mbar, (uint32_t)nrows * 6272u + 6144u);
            if (tid < nrows * 3) {
                int r = tid / 3, p = tid - r * 3;
                int f = r / 3, dd = r - f * 3;     // stage 1: r = dd, f = 0
                int lq = l - 1 + dd;
                size_t rowg = (size_t)(b * NLAT + lq) * NLON;
                const float* src = (STAGE == 1) ? (h0 + rowg)
                                                : (src_base<STAGE>() + (size_t)f * FOFF + rowg);
                uint32_t d = shb + r * SMW_A * 4;
                if (p == 0)      bulk_g2s(d,                    src + (NLON - HALO), HALO * 4, mbar);
                else if (p == 1) bulk_g2s(d + HALO * 4,         src,                 NLON * 4, mbar);
                else             bulk_g2s(d + (HALO + NLON) * 4, src,                HALO * 4, mbar);
            } else if (tid >= 32 && tid < 56) {
                int e2 = tid - 32;
                int kr = e2 >> 1, p = e2 & 1;
                int dd = kr >> 2, k = kr & 3;
                size_t ko = (size_t)(l * 5 + dd + 1) * NLON;
                uint32_t d = shKo + kr * KW_A * 4;
                if (p == 0) bulk_g2s(d,            Ks[k] + ko + (NLON - HALO), HALO * 4, mbar);
                else        bulk_g2s(d + HALO * 4, Ks[k] + ko,                 HALO * 4, mbar);
            }
        }
        if (STAGE == 1) {
            for (int e = tid; e < 6 * (SMW_A / 4); e += BLK) {
                int r = e / (SMW_A / 4);
                int q4 = (e - r * (SMW_A / 4)) * 4;
                int f = 1 + r / 3, dd = r - (f - 1) * 3;
                int lq = l - 1 + dd;
                size_t rowg = (size_t)(b * NLAT + lq) * NLON;
                int m = q4 - HALO;
                float4 x;
                if (m >= 0 && m + 3 < NLON) {
                    const float4 a4 = *(const float4*)(uv0 + 2 * (rowg + m));
                    const float4 c4 = *(const float4*)(uv0 + 2 * (rowg + m) + 4);
                    if (f == 1) { x.x=a4.x; x.y=a4.z; x.z=c4.x; x.w=c4.z; }
                    else        { x.x=a4.y; x.y=a4.w; x.z=c4.y; x.w=c4.w; }
                } else {
                    float t[4];
                    #pragma unroll
                    for (int i = 0; i < 4; ++i) {
                        int mm = m + i;
                        mm += (mm < 0) ? NLON : 0; mm -= (mm >= NLON) ? NLON : 0;
                        t[i] = uv0[2 * (rowg + mm) + (f - 1)];
                    }
                    x.x=t[0]; x.y=t[1]; x.z=t[2]; x.w=t[3];
                }
                *(float4*)(sh + (f * 3 + dd) * SMW_A + q4) = x;
            }
            __syncthreads();
        }
        mbar_wait(mbar);
        if (tid >= COMP) return;

        Acc a;
        #pragma unroll
        for (int i = 0; i < 4; ++i) { a.adu[i]=0.f; a.adv[i]=0.f; a.adh[i]=0.f; }
        int n0 = tid * 4, off0 = HALO + n0;
        const float* shK = sh + 9 * SMW_A;

        for (int dd = 0; dd < 3; ++dd) {
            int cnt = __ldg(&g_bcnt[l * 3 + dd]);
            if (cnt == 0) continue;
            int jl = __ldg(&g_bjl[l * 3 + dd]);
            int je = jl + cnt;
            jl = max(jl, -HALO); je = min(je, HALO);
            const float* kb = shK + dd * 4 * KW_A + HALO;
            seg_loop(kb, kb + KW_A, kb + 2*KW_A, kb + 3*KW_A,
                     sh + (0*3 + dd) * SMW_A + off0,
                     sh + (1*3 + dd) * SMW_A + off0,
                     sh + (2*3 + dd) * SMW_A + off0,
                     jl, je, a);
        }

        float fl = __ldg(fcor + l);
        const float* chp = sh + (0*3 + 1) * SMW_A + off0;
        const float* cup = sh + (1*3 + 1) * SMW_A + off0;
        const float* cvp = sh + (2*3 + 1) * SMW_A + off0;
        size_t rb = (size_t)(b * NLAT + l) * NLON + n0;
        #pragma unroll
        for (int i = 0; i < 4; ++i)
            rk_epilogue<STAGE>(rb + i, -a.adh[i], -a.adu[i] - fl*cvp[i],
                               -a.adv[i] + fl*cup[i], chp[i], cup[i], cvp[i],
                               h0, uv0, outH, outUV);
    }
}

template<int STAGE>
__global__ void __launch_bounds__(384)
reduceB_kernel(const float* __restrict__ h0, const float* __restrict__ uv0,
               const float* __restrict__ fcor,
               float* __restrict__ outH, float* __restrict__ outUV)
{
    int tid = threadIdx.x;
    if (tid >= 360) return;
    int rl = blockIdx.x, b = blockIdx.y;
    int lon = blockIdx.z * 360 + tid;
    int l = polar_map(rl);
    int task = b * NPOLAR + rl;

    float su = 0.f, sv = 0.f, sk = 0.f;
    for (int dd = 0; dd < 3; ++dd) {
        int cnt = __ldg(&g_bcnt[l * 3 + dd]);
        if (cnt == 0) continue;
        int steps = cnt >> 2;
        int per = (steps + NCHB - 1) / NCHB;
        int nact = (steps + per - 1) / per;
        for (int s = 0; s < nact; ++s) {
            const float* part = g_part +
                ((size_t)(dd * NCHB + s) * (NB * NPOLAR) + task) * (3 * NLON);
            su += __ldg(part + lon);
            sv += __ldg(part + NLON + lon);
            sk += __ldg(part + 2*NLON + lon);
        }
    }
    float fl = __ldg(fcor + l);
    size_t g = (size_t)(b * NLAT + l) * NLON + lon;
    float hc, uc, vc;
    if (STAGE == 1) { hc = h0[g]; uc = uv0[2*g]; vc = uv0[2*g+1]; }
    else {
        const float* c_ = src_base<STAGE>();
        hc = c_[g]; uc = c_[FOFF + g]; vc = c_[2*FOFF + g];
    }
    rk_epilogue<STAGE>(g, -sk, -su - fl*vc, -sv + fl*uc, hc, uc, vc,
                       h0, uv0, outH, outUV);
}

template<int STAGE>
static void run_stage(const float* h0, const float* uv0,
                      const float* Kgc, const float* Kgs,
                      const float* Kdc, const float* Kds, const float* fc,
                      float* outH, float* outUV)
{
    tend_kernel<STAGE><<<dim3(NPOLTASK + NINT, NB), BLK, SMEMSZ>>>(
        h0, uv0, Kgc, Kgs, Kdc, Kds, fc, outH, outUV);
    reduceB_kernel<STAGE><<<dim3(NPOLAR, NB, 4), 384>>>(h0, uv0, fc, outH, outUV);
}

extern "C" void kernel_launch(void* const* d_in, const int* in_sizes, int n_in,
                              void* d_out, int out_size)
{
    const float* h0  = (const float*)d_in[0];
    const float* uv0 = (const float*)d_in[1];
    const float* Kgc = (const float*)d_in[2];
    const float* Kgs = (const float*)d_in[3];
    const float* Kdc = (const float*)d_in[4];
    const float* Kds = (const float*)d_in[5];
    const float* fc  = (const float*)d_in[6];
    float* outH  = (float*)d_out;
    float* outUV = (float*)d_out + FOFF;

    static bool attr_set = false;
    if (!attr_set) {
        cudaFuncSetAttribute(tend_kernel<1>, cudaFuncAttributeMaxDynamicSharedMemorySize, SMEMSZ);
        cudaFuncSetAttribute(tend_kernel<2>, cudaFuncAttributeMaxDynamicSharedMemorySize, SMEMSZ);
        cudaFuncSetAttribute(tend_kernel<3>, cudaFuncAttributeMaxDynamicSharedMemorySize, SMEMSZ);
        cudaFuncSetAttribute(tend_kernel<4>, cudaFuncAttributeMaxDynamicSharedMemorySize, SMEMSZ);
        attr_set = true;
    }

    init_bounds<<<(NLAT * 3 + 127) / 128, 128>>>();

    run_stage<1>(h0, uv0, Kgc, Kgs, Kdc, Kds, fc, outH, outUV);
    run_stage<2>(h0, uv0, Kgc, Kgs, Kdc, Kds, fc, outH, outUV);
    run_stage<3>(h0, uv0, Kgc, Kgs, Kdc, Kds, fc, outH, outUV);
    run_stage<4>(h0, uv0, Kgc, Kgs, Kdc, Kds, fc, outH, outUV);

    (void)in_sizes; (void)n_in; (void)out_size;
}

// round 16
// speedup vs baseline: 1.0789x; 1.0789x over previous
#include <cuda_runtime.h>
#include <math.h>
#include <stdint.h>

#define NLAT 721
#define NLON 1440
#define NB   4
#define DT   0.01f
#define FOFF ((size_t)NB * NLAT * NLON)
#define DTH  (3.14159265358979323846 / 720.0)

#define LS     10
#define NPOLAR 20
#define NINT   701                       // rows 10..710
#define NCHB   4
#define NPOLTASK (NPOLAR * 3 * NCHB)     // 240

#define HALO  64
#define KW_A  (2 * HALO)                 // 128 floats per staged K row (interior)
#define SMW_A (NLON + 2 * HALO + 8)      // 1576 floats; row = 6304 B
#define SMW_B 2896                       // polar duplicated row; 11584 B
#define KW_B  368                        // max polar chunk taps (360) + pad
#define SMEM_CORE ((9 * SMW_A + 12 * KW_A) * 4)   // 62880 B (>= polar 40640)
#define MBAR_OFF  SMEM_CORE
#define SMEMSZ    (SMEM_CORE + 16)
#define BLK   384
#define COMP  360

static __device__ float g_c1[3 * FOFF];   // y0 + DT/2 k1
static __device__ float g_c2[3 * FOFF];   // y0 + DT/2 k2
static __device__ float g_c3[3 * FOFF];   // y0 + DT   k3
static __device__ float g_part[(size_t)(3 * NCHB) * NB * NPOLAR * 3 * NLON];
static __device__ int   g_bjl [NLAT * 3];
static __device__ int   g_bcnt[NLAT * 3];

__device__ __forceinline__ int polar_map(int rl) { return rl < 10 ? rl : 711 + (rl - 10); }

__device__ __forceinline__ uint32_t smem_u32(const void* p) {
    uint32_t a;
    asm("{ .reg .u64 t; cvta.to.shared.u64 t, %1; cvt.u32.u64 %0, t; }" : "=r"(a) : "l"(p));
    return a;
}
__device__ __forceinline__ void bulk_g2s(uint32_t dst, const void* src,
                                         uint32_t bytes, uint32_t mbar) {
    asm volatile(
        "cp.async.bulk.shared::cluster.global.mbarrier::complete_tx::bytes [%0], [%1], %2, [%3];"
        :: "r"(dst), "l"(src), "r"(bytes), "r"(mbar) : "memory");
}
__device__ __forceinline__ void mbar_init(uint32_t mbar, uint32_t cnt) {
    asm volatile("mbarrier.init.shared.b64 [%0], %1;" :: "r"(mbar), "r"(cnt) : "memory");
}
__device__ __forceinline__ void mbar_expect(uint32_t mbar, uint32_t bytes) {
    asm volatile("mbarrier.arrive.expect_tx.shared.b64 _, [%0], %1;"
                 :: "r"(mbar), "r"(bytes) : "memory");
}
__device__ __forceinline__ void mbar_wait(uint32_t mbar) {
    asm volatile(
        "{\n\t.reg .pred P;\n\t"
        "W_%=:\n\t"
        "mbarrier.try_wait.parity.acquire.cta.shared::cta.b64 P, [%0], 0, 0x989680;\n\t"
        "@P bra.uni D_%=;\n\t"
        "bra.uni W_%=;\n\t"
        "D_%=:\n\t}"
        :: "r"(mbar) : "memory");
}

__global__ void init_bounds()
{
    int idx = blockIdx.x * blockDim.x + threadIdx.x;
    if (idx >= NLAT * 3) return;
    int l = idx / 3, dd = idx - 3 * l;
    int jl = 0, cnt = 0;
    int lq = l - 1 + dd;
    if (lq >= 1 && lq <= NLAT - 2) {
        if (l == 0 || l == NLAT - 1) { jl = -720; cnt = 1440; }
        else {
            double tp = l * DTH, tq = lq * DTH;
            double cph = (cos(2.0 * DTH) - cos(tp) * cos(tq)) / (sin(tp) * sin(tq));
            if (cph < 1.0) {
                int W = 720;
                if (cph > -1.0) W = (int)(acos(cph) / DTH) + 1;
                if (W >= 716) { jl = -720; cnt = 1440; }
                else { jl = -((W + 3) & ~3); int je = (W + 4) & ~3; cnt = je - jl; }
            }
        }
    }
    g_bjl[idx] = jl; g_bcnt[idx] = cnt;
}

struct Acc { float adu[4], adv[4], adh[4]; };

// Correlation over j in [j0, j1), 4-aligned, all pointers into SMEM.
__device__ __forceinline__ void seg_loop(
    const float* kgc, const float* kgs, const float* kdc, const float* kds,
    const float* rh, const float* ru, const float* rv,
    int j0, int j1, Acc& a)
{
    if (j0 >= j1) return;
    float4 hA = *(const float4*)(rh + j0);
    float4 uA = *(const float4*)(ru + j0);
    float4 vA = *(const float4*)(rv + j0);
    for (int j = j0; j < j1; j += 4) {
        const float4 kc = *(const float4*)(kgc + j);
        const float4 ks = *(const float4*)(kgs + j);
        const float4 dc = *(const float4*)(kdc + j);
        const float4 dz = *(const float4*)(kds + j);
        float4 hB = *(const float4*)(rh + j + 4);
        float4 uB = *(const float4*)(ru + j + 4);
        float4 vB = *(const float4*)(rv + j + 4);
        float hb[8] = {hA.x,hA.y,hA.z,hA.w,hB.x,hB.y,hB.z,hB.w};
        float ub[8] = {uA.x,uA.y,uA.z,uA.w,uB.x,uB.y,uB.z,uB.w};
        float vb[8] = {vA.x,vA.y,vA.z,vA.w,vB.x,vB.y,vB.z,vB.w};
        float kcb[4] = {kc.x,kc.y,kc.z,kc.w};
        float ksb[4] = {ks.x,ks.y,ks.z,ks.w};
        float dcb[4] = {dc.x,dc.y,dc.z,dc.w};
        float dsb[4] = {dz.x,dz.y,dz.z,dz.w};
        #pragma unroll
        for (int jj = 0; jj < 4; ++jj)
            #pragma unroll
            for (int i = 0; i < 4; ++i) {
                a.adu[i] = fmaf(kcb[jj], hb[jj+i], a.adu[i]);
                a.adv[i] = fmaf(ksb[jj], hb[jj+i], a.adv[i]);
                a.adh[i] = fmaf(dcb[jj], ub[jj+i], a.adh[i]);
                a.adh[i] = fmaf(dsb[jj], vb[jj+i], a.adh[i]);
            }
        hA = hB; uA = uB; vA = vB;
    }
}

template<int STAGE>
__device__ __forceinline__ const float* src_base()
{
    return (STAGE == 2) ? g_c1 : (STAGE == 3) ? g_c2 : g_c3;
}

// RK epilogue. ch/cu/cv = stage-source center values (smem). For STAGE 1 they
// ARE y0 -> no global y0 reads. For STAGE 4 they are c3 values used to
// reconstruct k3 without a global read.
template<int STAGE>
__device__ __forceinline__ void rk_epilogue(
    size_t idx, float kh, float ku, float kv,
    float ch, float cu, float cv,
    const float* __restrict__ h0, const float* __restrict__ uv0,
    float* __restrict__ outH, float* __restrict__ outUV)
{
    if (STAGE == 1) {
        g_c1[idx]        = ch + 0.5f*DT*kh;
        g_c1[FOFF+idx]   = cu + 0.5f*DT*ku;
        g_c1[2*FOFF+idx] = cv + 0.5f*DT*kv;
        return;
    }
    float y0h = h0[idx], y0u = uv0[2*idx], y0v = uv0[2*idx+1];
    if (STAGE == 2) {
        g_c2[idx]        = y0h + 0.5f*DT*kh;
        g_c2[FOFF+idx]   = y0u + 0.5f*DT*ku;
        g_c2[2*FOFF+idx] = y0v + 0.5f*DT*kv;
    } else if (STAGE == 3) {
        g_c3[idx]        = y0h + DT*kh;
        g_c3[FOFF+idx]   = y0u + DT*ku;
        g_c3[2*FOFF+idx] = y0v + DT*kv;
    } else {
        const float i2 = 2.0f / DT, i1 = 1.0f / DT;
        float k1h = (g_c1[idx]        - y0h) * i2;
        float k1u = (g_c1[FOFF+idx]   - y0u) * i2;
        float k1v = (g_c1[2*FOFF+idx] - y0v) * i2;
        float k2h = (g_c2[idx]        - y0h) * i2;
        float k2u = (g_c2[FOFF+idx]   - y0u) * i2;
        float k2v = (g_c2[2*FOFF+idx] - y0v) * i2;
        float k3h = (ch - y0h) * i1;
        float k3u = (cu - y0u) * i1;
        float k3v = (cv - y0v) * i1;
        outH[idx] = y0h + (DT/6.f) * (k1h + 2.f*k2h + 2.f*k3h + kh);
        float2 o;
        o.x = y0u + (DT/6.f) * (k1u + 2.f*k2u + 2.f*k3u + ku);
        o.y = y0v + (DT/6.f) * (k1v + 2.f*k2v + 2.f*k3v + kv);
        reinterpret_cast<float2*>(outUV)[idx] = o;
    }
}

template<int STAGE>
__global__ void __launch_bounds__(BLK, 3)
tend_kernel(const float* __restrict__ h0, const float* __restrict__ uv0,
            const float* __restrict__ Kgc, const float* __restrict__ Kgs,
            const float* __restrict__ Kdc, const float* __restrict__ Kds,
            const float* __restrict__ fcor,
            float* __restrict__ outH, float* __restrict__ outUV)
{
    extern __shared__ __align__(16) float sh[];
    int tid = threadIdx.x, bx = blockIdx.x, b = blockIdx.y;
    const float* Ks[4] = {Kgc, Kgs, Kdc, Kds};
    uint32_t shb  = smem_u32(sh);
    uint32_t mbar = shb + MBAR_OFF;

    if (tid == 0) mbar_init(mbar, 1);
    __syncthreads();

    if (bx < NPOLTASK) {
        // ---------------- polar chunk (rows 0..9, 711..720) ----------------
        int rl = bx / (3 * NCHB), rem = bx - rl * 3 * NCHB;
        int dd = rem / NCHB, c = rem - dd * NCHB;
        int l = polar_map(rl);
        int cnt = __ldg(&g_bcnt[l * 3 + dd]);
        int jl = __ldg(&g_bjl[l * 3 + dd]);
        int steps = cnt >> 2;
        int per = (steps + NCHB - 1) / NCHB;
        int s0 = c * per, s1 = min(steps, s0 + per);
        if (cnt == 0 || s0 >= s1) return;
        int jA = jl + 4 * s0, jB = jl + 4 * s1;
        int ntap = jB - jA;
        int neg_len = max(0, min(jB, 0) - jA);
        int pos_len = max(0, jB - max(jA, 0));

        int lq = l - 1 + dd;
        size_t rowg = (size_t)(b * NLAT + lq) * NLON;
        size_t ko   = (size_t)(l * 5 + dd + 1) * NLON;
        uint32_t shKo = shb + 3 * SMW_B * 4;

        if (tid == 0) {
            uint32_t nfld  = (STAGE == 1) ? 1 : 3;
            uint32_t bytes = nfld * 11520u + 16u * (uint32_t)ntap;
            mbar_expect(mbar, bytes);
            #pragma unroll
            for (int f = 0; f < 3; ++f) {
                if (STAGE == 1 && f > 0) break;
                const float* src = (STAGE == 1) ? (h0 + rowg)
                                                : (src_base<STAGE>() + (size_t)f * FOFF + rowg);
                uint32_t d = shb + f * SMW_B * 4;
                bulk_g2s(d,            src + 720, 2880, mbar);
                bulk_g2s(d + 2880,     src,       5760, mbar);
                bulk_g2s(d + 8640,     src,       2880, mbar);
            }
            #pragma unroll
            for (int k = 0; k < 4; ++k) {
                uint32_t d = shKo + k * KW_B * 4;
                if (neg_len > 0) bulk_g2s(d, Ks[k] + ko + NLON + jA, neg_len * 4, mbar);
                if (pos_len > 0) bulk_g2s(d + neg_len * 4, Ks[k] + ko + max(jA, 0),
                                          pos_len * 4, mbar);
            }
        }
        if (STAGE == 1) {
            for (int e = tid; e < 2 * (NLON / 4); e += BLK) {
                int f = 1 + e / (NLON / 4);
                int m = (e - (f - 1) * (NLON / 4)) * 4;
                const float4 a4 = *(const float4*)(uv0 + 2 * (rowg + m));
                const float4 c4 = *(const float4*)(uv0 + 2 * (rowg + m) + 4);
                float4 x;
                if (f == 1) { x.x=a4.x; x.y=a4.z; x.z=c4.x; x.w=c4.z; }
                else        { x.x=a4.y; x.y=a4.w; x.z=c4.y; x.w=c4.w; }
                int q = m + 720; if (q >= NLON) q -= NLON;
                float* dst = sh + f * SMW_B;
                *(float4*)(dst + q) = x;
                *(float4*)(dst + q + NLON) = x;
            }
            __syncthreads();
        }
        mbar_wait(mbar);
        if (tid >= COMP) return;

        int n0 = tid * 4;
        Acc a;
        #pragma unroll
        for (int i = 0; i < 4; ++i) { a.adu[i]=0.f; a.adv[i]=0.f; a.adh[i]=0.f; }
        const float* shK = sh + 3 * SMW_B;
        seg_loop(shK + 0*KW_B - jA, shK + 1*KW_B - jA,
                 shK + 2*KW_B - jA, shK + 3*KW_B - jA,
                 sh + 720 + n0, sh + SMW_B + 720 + n0, sh + 2*SMW_B + 720 + n0,
                 jA, jB, a);

        int task = b * NPOLAR + rl;
        float* part = g_part + ((size_t)(dd * NCHB + c) * (NB * NPOLAR) + task) * (3 * NLON);
        *(float4*)(part + 0*NLON + n0) = *(float4*)a.adu;
        *(float4*)(part + 1*NLON + n0) = *(float4*)a.adv;
        *(float4*)(part + 2*NLON + n0) = *(float4*)a.adh;
    } else {
        // ---------------- interior full row (l in [10, 710]) ----------------
        int li = bx - NPOLTASK;
        int l = (li & 1) ? (710 - (li >> 1)) : (LS + (li >> 1));
        uint32_t shKo = shb + 9 * SMW_A * 4;

        if (tid == 0) {
            uint32_t nfld  = (STAGE == 1) ? 1 : 3;
            uint32_t bytes = nfld * 3u * 6272u + 6144u;
            mbar_expect(mbar, bytes);
            #pragma unroll
            for (int f = 0; f < 3; ++f) {
                if (STAGE == 1 && f > 0) break;
                #pragma unroll
                for (int dd = 0; dd < 3; ++dd) {
                    int lq = l - 1 + dd;
                    size_t rowg = (size_t)(b * NLAT + lq) * NLON;
                    const float* src = (STAGE == 1) ? (h0 + rowg)
                                                    : (src_base<STAGE>() + (size_t)f * FOFF + rowg);
                    uint32_t d = shb + (f * 3 + dd) * SMW_A * 4;
                    bulk_g2s(d,        src + (NLON - HALO), HALO * 4, mbar);
                    bulk_g2s(d + HALO * 4, src, NLON * 4, mbar);
                    bulk_g2s(d + (HALO + NLON) * 4, src, HALO * 4, mbar);
                }
            }
            #pragma unroll
            for (int dd = 0; dd < 3; ++dd) {
                size_t ko = (size_t)(l * 5 + dd + 1) * NLON;
                #pragma unroll
                for (int k = 0; k < 4; ++k) {
                    uint32_t d = shKo + (dd * 4 + k) * KW_A * 4;
                    bulk_g2s(d,       Ks[k] + ko + (NLON - HALO), HALO * 4, mbar);
                    bulk_g2s(d + HALO * 4, Ks[k] + ko, HALO * 4, mbar);
                }
            }
        }
        if (STAGE == 1) {
            for (int e = tid; e < 6 * (SMW_A / 4); e += BLK) {
                int r = e / (SMW_A / 4);
                int q4 = (e - r * (SMW_A / 4)) * 4;
                int f = 1 + r / 3, dd = r - (f - 1) * 3;
                int lq = l - 1 + dd;
                size_t rowg = (size_t)(b * NLAT + lq) * NLON;
                int m = q4 - HALO;
                float4 x;
                if (m >= 0 && m + 3 < NLON) {
                    const float4 a4 = *(const float4*)(uv0 + 2 * (rowg + m));
                    const float4 c4 = *(const float4*)(uv0 + 2 * (rowg + m) + 4);
                    if (f == 1) { x.x=a4.x; x.y=a4.z; x.z=c4.x; x.w=c4.z; }
                    else        { x.x=a4.y; x.y=a4.w; x.z=c4.y; x.w=c4.w; }
                } else {
                    float t[4];
                    #pragma unroll
                    for (int i = 0; i < 4; ++i) {
                        int mm = m + i;
                        mm += (mm < 0) ? NLON : 0; mm -= (mm >= NLON) ? NLON : 0;
                        t[i] = uv0[2 * (rowg + mm) + (f - 1)];
                    }
                    x.x=t[0]; x.y=t[1]; x.z=t[2]; x.w=t[3];
                }
                *(float4*)(sh + (f * 3 + dd) * SMW_A + q4) = x;
            }
            __syncthreads();
        }
        mbar_wait(mbar);
        if (tid >= COMP) return;

        Acc a;
        #pragma unroll
        for (int i = 0; i < 4; ++i) { a.adu[i]=0.f; a.adv[i]=0.f; a.adh[i]=0.f; }
        int n0 = tid * 4, off0 = HALO + n0;
        const float* shK = sh + 9 * SMW_A;

        for (int dd = 0; dd < 3; ++dd) {
            int cnt = __ldg(&g_bcnt[l * 3 + dd]);
            if (cnt == 0) continue;
            int jl = __ldg(&g_bjl[l * 3 + dd]);
            int je = jl + cnt;
            jl = max(jl, -HALO); je = min(je, HALO);
            const float* kb = shK + dd * 4 * KW_A + HALO;
            seg_loop(kb, kb + KW_A, kb + 2*KW_A, kb + 3*KW_A,
                     sh + (0*3 + dd) * SMW_A + off0,
                     sh + (1*3 + dd) * SMW_A + off0,
                     sh + (2*3 + dd) * SMW_A + off0,
                     jl, je, a);
        }

        float fl = __ldg(fcor + l);
        const float* chp = sh + (0*3 + 1) * SMW_A + off0;
        const float* cup = sh + (1*3 + 1) * SMW_A + off0;
        const float* cvp = sh + (2*3 + 1) * SMW_A + off0;
        size_t rb = (size_t)(b * NLAT + l) * NLON + n0;
        #pragma unroll
        for (int i = 0; i < 4; ++i)
            rk_epilogue<STAGE>(rb + i, -a.adh[i], -a.adu[i] - fl*cvp[i],
                               -a.adv[i] + fl*cup[i], chp[i], cup[i], cvp[i],
                               h0, uv0, outH, outUV);
    }
}

template<int STAGE>
__global__ void __launch_bounds__(384)
reduceB_kernel(const float* __restrict__ h0, const float* __restrict__ uv0,
               const float* __restrict__ fcor,
               float* __restrict__ outH, float* __restrict__ outUV)
{
    int tid = threadIdx.x;
    if (tid >= 360) return;
    int rl = blockIdx.x, b = blockIdx.y;
    int lon = blockIdx.z * 360 + tid;
    int l = polar_map(rl);
    int task = b * NPOLAR + rl;

    float su = 0.f, sv = 0.f, sk = 0.f;
    for (int dd = 0; dd < 3; ++dd) {
        int cnt = __ldg(&g_bcnt[l * 3 + dd]);
        if (cnt == 0) continue;
        int steps = cnt >> 2;
        int per = (steps + NCHB - 1) / NCHB;
        int nact = (steps + per - 1) / per;
        for (int s = 0; s < nact; ++s) {
            const float* part = g_part +
                ((size_t)(dd * NCHB + s) * (NB * NPOLAR) + task) * (3 * NLON);
            su += __ldg(part + lon);
            sv += __ldg(part + NLON + lon);
            sk += __ldg(part + 2*NLON + lon);
        }
    }
    float fl = __ldg(fcor + l);
    size_t g = (size_t)(b * NLAT + l) * NLON + lon;
    float hc, uc, vc;
    if (STAGE == 1) { hc = h0[g]; uc = uv0[2*g]; vc = uv0[2*g+1]; }
    else {
        const float* c_ = src_base<STAGE>();
        hc = c_[g]; uc = c_[FOFF + g]; vc = c_[2*FOFF + g];
    }
    rk_epilogue<STAGE>(g, -sk, -su - fl*vc, -sv + fl*uc, hc, uc, vc,
                       h0, uv0, outH, outUV);
}

template<int STAGE>
static void run_stage(const float* h0, const float* uv0,
                      const float* Kgc, const float* Kgs,
                      const float* Kdc, const float* Kds, const float* fc,
                      float* outH, float* outUV)
{
    tend_kernel<STAGE><<<dim3(NPOLTASK + NINT, NB), BLK, SMEMSZ>>>(
        h0, uv0, Kgc, Kgs, Kdc, Kds, fc, outH, outUV);
    reduceB_kernel<STAGE><<<dim3(NPOLAR, NB, 4), 384>>>(h0, uv0, fc, outH, outUV);
}

extern "C" void kernel_launch(void* const* d_in, const int* in_sizes, int n_in,
                              void* d_out, int out_size)
{
    const float* h0  = (const float*)d_in[0];
    const float* uv0 = (const float*)d_in[1];
    const float* Kgc = (const float*)d_in[2];
    const float* Kgs = (const float*)d_in[3];
    const float* Kdc = (const float*)d_in[4];
    const float* Kds = (const float*)d_in[5];
    const float* fc  = (const float*)d_in[6];
    float* outH  = (float*)d_out;
    float* outUV = (float*)d_out + FOFF;

    static bool attr_set = false;
    if (!attr_set) {
        cudaFuncSetAttribute(tend_kernel<1>, cudaFuncAttributeMaxDynamicSharedMemorySize, SMEMSZ);
        cudaFuncSetAttribute(tend_kernel<2>, cudaFuncAttributeMaxDynamicSharedMemorySize, SMEMSZ);
        cudaFuncSetAttribute(tend_kernel<3>, cudaFuncAttributeMaxDynamicSharedMemorySize, SMEMSZ);
        cudaFuncSetAttribute(tend_kernel<4>, cudaFuncAttributeMaxDynamicSharedMemorySize, SMEMSZ);
        attr_set = true;
    }

    init_bounds<<<(NLAT * 3 + 127) / 128, 128>>>();

    run_stage<1>(h0, uv0, Kgc, Kgs, Kdc, Kds, fc, outH, outUV);
    run_stage<2>(h0, uv0, Kgc, Kgs, Kdc, Kds, fc, outH, outUV);
    run_stage<3>(h0, uv0, Kgc, Kgs, Kdc, Kds, fc, outH, outUV);
    run_stage<4>(h0, uv0, Kgc, Kgs, Kdc, Kds, fc, outH, outUV);

    (void)in_sizes; (void)n_in; (void)out_size;
}